// round 16
// baseline (speedup 1.0000x reference)
#include <cuda_runtime.h>

// Shapes: x (8,96,256,256) f32. BC=768 channel-slices of 256x256.
// Outputs: xlo (768,128,128) then xhi_dir (768,4,128,128), concatenated in d_out.

#define N_BC   768
#define NPIX   65536           // 256*256
#define NHALF  32768           // 128*256
#define NQ     16384           // 128*128

__device__ float g_xhi[50331648];   // 768*256*256  (also x-hi band)
__device__ float g_s0[25165824];    // 768*128*256  (K1a tmp, then f0-conv even rows)
__device__ float g_s1[25165824];    // 768*128*256  (f1-conv even rows)

// ---------------------------------------------------------------------------
// K1a: row filter (5-tap h, wrap) at even output rows -> tmp (in g_s0)
// tmp[bc,i,w] = sum_u h[u] x[bc,(2i+u-2)&255,w]
// ---------------------------------------------------------------------------
__global__ __launch_bounds__(256) void k1a(const float* __restrict__ x,
                                           const float* __restrict__ hf) {
    int t  = blockIdx.x * 256 + threadIdx.x;     // 6,291,456 threads
    int w4 = t & 63;
    int i  = (t >> 6) & 127;
    int bc = t >> 13;
    float hc[5];
#pragma unroll
    for (int u = 0; u < 5; u++) hc[u] = __ldg(hf + u);
    const float* xb = x + (size_t)bc * NPIX;
    float4 acc = make_float4(0.f, 0.f, 0.f, 0.f);
    int r0 = 2 * i - 2;
#pragma unroll
    for (int u = 0; u < 5; u++) {
        int r = (r0 + u) & 255;
        float4 v = __ldg((const float4*)(xb + r * 256) + w4);
        acc.x += hc[u] * v.x; acc.y += hc[u] * v.y;
        acc.z += hc[u] * v.z; acc.w += hc[u] * v.w;
    }
    ((float4*)(g_s0 + (size_t)bc * NHALF + i * 256))[w4] = acc;
}

// ---------------------------------------------------------------------------
// K1b: column filter at even cols -> xlo (first output block)
// xlo[bc,i,j] = sum_v h[v] tmp[bc,i,(2j+v-2)&255]
// ---------------------------------------------------------------------------
__global__ __launch_bounds__(256) void k1b(const float* __restrict__ hf,
                                           float* __restrict__ out_lo) {
    int t  = blockIdx.x * 256 + threadIdx.x;     // 12,582,912 threads
    int j  = t & 127;
    int i  = (t >> 7) & 127;
    int bc = t >> 14;
    float hc[5];
#pragma unroll
    for (int v = 0; v < 5; v++) hc[v] = __ldg(hf + v);
    const float* tr = g_s0 + (size_t)bc * NHALF + i * 256;
    int c0 = 2 * j - 2;
    float acc = 0.f;
#pragma unroll
    for (int v = 0; v < 5; v++) acc += hc[v] * __ldg(tr + ((c0 + v) & 255));
    out_lo[(size_t)bc * NQ + i * 128 + j] = acc;
}

// ---------------------------------------------------------------------------
// K2: xhi = x - sepfilt(up(xlo), g).  Parity kills half the 7 taps per dim:
// even out-row uses g[1],g[3],g[5]; odd out-row uses g[0],g[2],g[4],g[6].
// Each thread produces a 2x2 output block from a 4x4 xlo patch.
// ---------------------------------------------------------------------------
__global__ __launch_bounds__(256) void k2(const float* __restrict__ x,
                                          const float* __restrict__ gf,
                                          const float* __restrict__ xlo) {
    int t  = blockIdx.x * 256 + threadIdx.x;     // 12,582,912 threads
    int j  = t & 127;
    int i  = (t >> 7) & 127;
    int bc = t >> 14;
    float g0 = __ldg(gf + 0), g1 = __ldg(gf + 1), g2 = __ldg(gf + 2),
          g3 = __ldg(gf + 3), g4 = __ldg(gf + 4), g5 = __ldg(gf + 5),
          g6 = __ldg(gf + 6);
    const float* lo = xlo + (size_t)bc * NQ;
    float X[4][4];
#pragma unroll
    for (int r = 0; r < 4; r++) {
        int rr = (i - 1 + r) & 127;
#pragma unroll
        for (int c = 0; c < 4; c++) {
            int cc = (j - 1 + c) & 127;
            X[r][c] = __ldg(lo + rr * 128 + cc);
        }
    }
    float So[4], Se[4];
#pragma unroll
    for (int r = 0; r < 4; r++) {
        So[r] = g1 * X[r][0] + g3 * X[r][1] + g5 * X[r][2];
        Se[r] = g0 * X[r][0] + g2 * X[r][1] + g4 * X[r][2] + g6 * X[r][3];
    }
    float Gee = g1 * So[0] + g3 * So[1] + g5 * So[2];
    float Geo = g1 * Se[0] + g3 * Se[1] + g5 * Se[2];
    float Goe = g0 * So[0] + g2 * So[1] + g4 * So[2] + g6 * So[3];
    float Goo = g0 * Se[0] + g2 * Se[1] + g4 * Se[2] + g6 * Se[3];

    const float* xb = x + (size_t)bc * NPIX;
    float* hb = g_xhi + (size_t)bc * NPIX;
    float2 xt = __ldg((const float2*)(xb + (2 * i) * 256) + j);
    float2 xu = __ldg((const float2*)(xb + (2 * i + 1) * 256) + j);
    ((float2*)(hb + (2 * i) * 256))[j]     = make_float2(xt.x - Gee, xt.y - Geo);
    ((float2*)(hb + (2 * i + 1) * 256))[j] = make_float2(xu.x - Goe, xu.y - Goo);
}

// ---------------------------------------------------------------------------
// K3: 7x7 wrap conv of xhi at EVEN rows, exploiting f0's support
// (center + 24 odd-parity taps) and f1 = center - odd_sum.
// Tile: 8 output i-rows x full 256 cols; smem holds 21 input rows.
// ---------------------------------------------------------------------------
__global__ __launch_bounds__(256) void k3(const float* __restrict__ f0) {
    __shared__ float xs[21][256];
    __shared__ float fs[49];
    int bid = blockIdx.x;                        // 12288 = 768 * 16
    int ig = bid & 15;
    int bc = bid >> 4;
    int tid = threadIdx.x;
    if (tid < 49) fs[tid] = __ldg(f0 + tid);
    const float* hb = g_xhi + (size_t)bc * NPIX;
    int i0 = ig * 8;
    for (int idx = tid; idx < 21 * 64; idx += 256) {
        int tr = idx >> 6, c4 = idx & 63;
        int r = (2 * i0 - 3 + tr) & 255;
        ((float4*)xs[tr])[c4] = __ldg((const float4*)(hb + r * 256) + c4);
    }
    __syncthreads();

    int tx = tid & 31, ty = tid >> 5;
    int i = i0 + ty;
    float* s0b = g_s0 + (size_t)bc * NHALF + i * 256;
    float* s1b = g_s1 + (size_t)bc * NHALF + i * 256;
    float fc = fs[24];                           // f0[3][3]
#pragma unroll
    for (int dw = 0; dw < 8; dw++) {
        int w = tx + 32 * dw;
        float acc = 0.f;
#pragma unroll
        for (int u = 0; u < 7; u++) {
            const float* row = xs[2 * ty + u];
#pragma unroll
            for (int v = (u & 1) ^ 1; v < 7; v += 2)   // (u+v) odd taps
                acc += fs[u * 7 + v] * row[(w + v - 3) & 255];
        }
        float c = fc * xs[2 * ty + 3][w];
        s0b[w] = c + acc;
        s1b[w] = c - acc;
    }
}

// ---------------------------------------------------------------------------
// K4: direction subbands. sub_{2p+f}[h,j] reads s_p along a sheared
// parallelogram: value = s_p[(h+2j+u-3)&127, (6j+2h+2u+v-9)&255].
// Pre-shear into smem: S[t][c] = s_p[(R0+t)&127, (C0+2t+c)&255],
// tap read = S[a+2b+u][2b+v]  (t=a+2b+u, c=2b+v).  Lanes along a ->
// LDS stride 69 (odd) = conflict-free.  Output staged in smem, written
// coalesced.  f0T output = center+odd, f1T = center-odd.
// ---------------------------------------------------------------------------
#define K4LDC 69
__global__ __launch_bounds__(256) void k4(const float* __restrict__ f0,
                                          float* __restrict__ out_hi) {
    __shared__ float S[100 * K4LDC];
    __shared__ float fts[49];
    __shared__ float Osm[2][32][33];
    int bid = blockIdx.x;                        // 24576 = 2*768*16
    int jg = bid & 3, hg = (bid >> 2) & 3;
    int pbc = bid >> 4;
    int p = (pbc >= 768) ? 1 : 0;
    int bc = pbc - p * 768;
    int tid = threadIdx.x;
    if (tid < 49) {                              // transpose: FT[u][v] = f0[v][u]
        int u = tid / 7, v = tid - u * 7;
        fts[tid] = __ldg(f0 + v * 7 + u);
    }
    int h0 = hg * 32, j0 = jg * 32;
    const float* sp = (p ? g_s1 : g_s0) + (size_t)bc * NHALF;
    int R0 = (h0 + 2 * j0 - 3) & 127;
    int C0 = (6 * j0 + 2 * h0 - 9) & 255;
    for (int idx = tid; idx < 100 * K4LDC; idx += 256) {
        int t = idx / K4LDC;
        int c = idx - t * K4LDC;
        int r = (R0 + t) & 127;
        int col = (C0 + 2 * t + c) & 255;
        S[idx] = __ldg(sp + r * 256 + col);
    }
    __syncthreads();

    int a = tid & 31, bg = tid >> 5;
    float fc = fts[24];
#pragma unroll
    for (int bi = 0; bi < 4; bi++) {
        int b = bg * 4 + bi;
        int rbase = a + 2 * b;
        int cbase = 2 * b;
        float acc = 0.f;
#pragma unroll
        for (int u = 0; u < 7; u++) {
            const float* row = &S[(rbase + u) * K4LDC + cbase];
#pragma unroll
            for (int v = (u & 1) ^ 1; v < 7; v += 2)
                acc += fts[u * 7 + v] * row[v];
        }
        float c = fc * S[(rbase + 3) * K4LDC + cbase + 3];
        Osm[0][a][b] = c + acc;     // f0^T subband
        Osm[1][a][b] = c - acc;     // f1^T subband
    }
    __syncthreads();

    size_t base = (size_t)bc * 4 * NQ;
    for (int k = tid; k < 1024; k += 256) {
        int aa = k >> 5, bb = k & 31;
        size_t pos = (size_t)(h0 + aa) * 128 + (j0 + bb);
        out_hi[base + (size_t)(2 * p + 0) * NQ + pos] = Osm[0][aa][bb];
        out_hi[base + (size_t)(2 * p + 1) * NQ + pos] = Osm[1][aa][bb];
    }
}

// ---------------------------------------------------------------------------
extern "C" void kernel_launch(void* const* d_in, const int* in_sizes, int n_in,
                              void* d_out, int out_size) {
    (void)in_sizes; (void)n_in; (void)out_size;
    const float* x  = (const float*)d_in[0];
    const float* hf = (const float*)d_in[1];
    const float* gf = (const float*)d_in[2];
    const float* f0 = (const float*)d_in[3];
    // d_in[4] (f1) is derived analytically: f1 = f0 * (-1)^(u+v) on support.
    float* out    = (float*)d_out;
    float* out_lo = out;                  // 768*128*128
    float* out_hi = out + 12582912;       // 768*4*128*128

    k1a<<<24576, 256>>>(x, hf);
    k1b<<<49152, 256>>>(hf, out_lo);
    k2 <<<49152, 256>>>(x, gf, out_lo);
    k3 <<<12288, 256>>>(f0);
    k4 <<<24576, 256>>>(f0, out_hi);
}

// round 17
// speedup vs baseline: 1.2217x; 1.2217x over previous
#include <cuda_runtime.h>

// Shapes: x (8,96,256,256) f32. BC=768 channel-slices of 256x256.
// Outputs: xlo (768,128,128) then xhi_dir (768,4,128,128), concatenated in d_out.

#define N_BC   768
#define NPIX   65536           // 256*256
#define NHALF  32768           // 128*256
#define NQ     16384           // 128*128

__device__ float g_s0[25165824];    // 768*128*256  (f0-conv of xhi at even rows)
__device__ float g_s1[25165824];    // 768*128*256  (f1-conv of xhi at even rows)

// ---------------------------------------------------------------------------
// K1: fused separable 5-tap lowpass + 2x2 decimation: x -> xlo.
// Block = (bc, ig): output rows i0..i0+7 x 128 cols.
// Vertical at even rows into T (smem), then horizontal at even cols.
// ---------------------------------------------------------------------------
__global__ __launch_bounds__(256) void k1(const float* __restrict__ x,
                                          const float* __restrict__ hf,
                                          float* __restrict__ out_lo) {
    __shared__ float xs[19][256];
    __shared__ float T[8][256];
    int bid = blockIdx.x;                        // 12288 = 768*16
    int ig = bid & 15, bc = bid >> 4;
    int tid = threadIdx.x;
    int i0 = ig * 8;
    const float* xb = x + (size_t)bc * NPIX;
    for (int idx = tid; idx < 19 * 64; idx += 256) {
        int tr = idx >> 6, c4 = idx & 63;
        int r = (2 * i0 - 2 + tr) & 255;
        ((float4*)xs[tr])[c4] = __ldg((const float4*)(xb + r * 256) + c4);
    }
    float h0 = __ldg(hf), h1 = __ldg(hf + 1), h2 = __ldg(hf + 2),
          h3 = __ldg(hf + 3), h4 = __ldg(hf + 4);
    __syncthreads();
    {
        int w = tid;
#pragma unroll
        for (int dy = 0; dy < 8; dy++) {
            T[dy][w] = h0 * xs[2 * dy][w] + h1 * xs[2 * dy + 1][w] +
                       h2 * xs[2 * dy + 2][w] + h3 * xs[2 * dy + 3][w] +
                       h4 * xs[2 * dy + 4][w];
        }
    }
    __syncthreads();
    float* ob = out_lo + (size_t)bc * NQ + i0 * 128;
    for (int idx = tid; idx < 1024; idx += 256) {
        int dy = idx >> 7, j = idx & 127;
        int c0 = 2 * j - 2;
        float acc = h0 * T[dy][c0 & 255] + h1 * T[dy][(c0 + 1) & 255] +
                    h2 * T[dy][(c0 + 2) & 255] + h3 * T[dy][(c0 + 3) & 255] +
                    h4 * T[dy][(c0 + 4) & 255];
        ob[dy * 128 + j] = acc;
    }
}

// ---------------------------------------------------------------------------
// K23: fused (xhi = x - sepfilt(up(xlo), g)) + 7x7 wrap conv at even rows.
// Block = (bc, ig): s-rows i0..i0+7 x 256 cols.
//   xh[21][256] : x tile (xhi rows 2i0-3..2i0+17), updated in place to xhi
//   lo[14][128] : xlo rows i0-3..i0+10
//   V [21][128] : vertical g-stage of up(xlo) at xhi rows
// Conv is column-threaded: thread = column w, computes all 8 outputs with
// per-row reuse: 81 LDS / 8 outputs (vs 200 before). f0 taps live in regs.
// s0 = center + odd_taps, s1 = center - odd_taps (f1 = f0*(-1)^(u+v)).
// ---------------------------------------------------------------------------
__global__ __launch_bounds__(256) void k23(const float* __restrict__ x,
                                           const float* __restrict__ gf,
                                           const float* __restrict__ f0,
                                           const float* __restrict__ xlo) {
    __shared__ float xh[21][256];
    __shared__ float lo[14][128];
    __shared__ float V[21][128];
    int bid = blockIdx.x;                        // 12288 = 768*16
    int ig = bid & 15, bc = bid >> 4;
    int tid = threadIdx.x;
    int i0 = ig * 8;

    const float* xb = x + (size_t)bc * NPIX;
    for (int idx = tid; idx < 21 * 64; idx += 256) {
        int tr = idx >> 6, c4 = idx & 63;
        int r = (2 * i0 - 3 + tr) & 255;
        ((float4*)xh[tr])[c4] = __ldg((const float4*)(xb + r * 256) + c4);
    }
    const float* lob = xlo + (size_t)bc * NQ;
    for (int idx = tid; idx < 14 * 32; idx += 256) {
        int lr = idx >> 5, c4 = idx & 31;
        int m = (i0 - 3 + lr) & 127;
        ((float4*)lo[lr])[c4] = __ldg((const float4*)(lob + m * 128) + c4);
    }
    float g0 = __ldg(gf), g1 = __ldg(gf + 1), g2 = __ldg(gf + 2),
          g3 = __ldg(gf + 3), g4 = __ldg(gf + 4), g5 = __ldg(gf + 5),
          g6 = __ldg(gf + 6);
    __syncthreads();

    // Vertical stage. xhi row rg = 2i0-3+tr: tr odd <=> rg even.
    //  rg even (tr odd):  taps g1,g3,g5 at xlo rows -> lo[(tr+1)/2 + {0,1,2}]
    //  rg odd  (tr even): taps g0,g2,g4,g6 at lo[tr/2 + {0,1,2,3}]
    for (int idx = tid; idx < 21 * 128; idx += 256) {
        int tr = idx >> 7, jc = idx & 127;
        float v;
        if (tr & 1) {
            int l = (tr + 1) >> 1;
            v = g1 * lo[l][jc] + g3 * lo[l + 1][jc] + g5 * lo[l + 2][jc];
        } else {
            int l = tr >> 1;
            v = g0 * lo[l][jc] + g2 * lo[l + 1][jc] + g4 * lo[l + 2][jc] +
                g6 * lo[l + 3][jc];
        }
        V[tr][jc] = v;
    }
    __syncthreads();

    // Horizontal stage + subtraction: xh becomes xhi.
    {
        int w = tid;
        int n = w >> 1;
        int nm1 = (n - 1) & 127, np1 = (n + 1) & 127, np2 = (n + 2) & 127;
#pragma unroll
        for (int tr = 0; tr < 21; tr++) {
            float s;
            if (w & 1)
                s = g0 * V[tr][nm1] + g2 * V[tr][n] + g4 * V[tr][np1] +
                    g6 * V[tr][np2];
            else
                s = g1 * V[tr][nm1] + g3 * V[tr][n] + g5 * V[tr][np1];
            xh[tr][w] -= s;
        }
    }
    __syncthreads();

    // Conv, column-threaded.
    float f[49];
#pragma unroll
    for (int q = 0; q < 49; q++) f[q] = __ldg(f0 + q);
    {
        int w = tid;
        int wm3 = (w - 3) & 255, wm2 = (w - 2) & 255, wm1 = (w - 1) & 255;
        int wp1 = (w + 1) & 255, wp2 = (w + 2) & 255, wp3 = (w + 3) & 255;
        float acc[8], cen[8];
#pragma unroll
        for (int dy = 0; dy < 8; dy++) { acc[dy] = 0.f; cen[dy] = 0.f; }
#pragma unroll
        for (int tr = 0; tr < 21; tr++) {
            if (tr & 1) {               // u odd: v in {0,2,4,6}; center at u==3
                float b0 = xh[tr][wm3], b1 = xh[tr][wm1];
                float b2 = xh[tr][wp1], b3 = xh[tr][wp3];
#pragma unroll
                for (int dy = 0; dy < 8; dy++) {
                    int u = tr - 2 * dy;
                    if (u >= 1 && u <= 5) {
                        acc[dy] += f[u * 7 + 0] * b0 + f[u * 7 + 2] * b1 +
                                   f[u * 7 + 4] * b2 + f[u * 7 + 6] * b3;
                        if (u == 3) cen[dy] = f[24] * xh[tr][w];
                    }
                }
            } else {                    // u even: v in {1,3,5}
                float b0 = xh[tr][wm2], b1 = xh[tr][w], b2 = xh[tr][wp2];
#pragma unroll
                for (int dy = 0; dy < 8; dy++) {
                    int u = tr - 2 * dy;
                    if (u >= 0 && u <= 6) {
                        acc[dy] += f[u * 7 + 1] * b0 + f[u * 7 + 3] * b1 +
                                   f[u * 7 + 5] * b2;
                    }
                }
            }
        }
        float* s0b = g_s0 + (size_t)bc * NHALF + i0 * 256 + w;
        float* s1b = g_s1 + (size_t)bc * NHALF + i0 * 256 + w;
#pragma unroll
        for (int dy = 0; dy < 8; dy++) {
            s0b[dy * 256] = cen[dy] + acc[dy];
            s1b[dy * 256] = cen[dy] - acc[dy];
        }
    }
}

// ---------------------------------------------------------------------------
// K4: direction subbands via double-sheared staging.
// Output (h,j), tap (u,v): s_p[(h+2j+u-3)&127, (6j+2h+2u+v-9)&255].
// Substituting rho = a+u-v+5 (u-v odd => rho-a-5 odd, range 0..10; center 5)
// and gamma = 2b+v gives T[rho][gamma] = s_p[(R0+rho+gamma)&127,
// (C0+2rho+3gamma)&255] with R0=h0+2j0-8, C0=6j0+2h0-19.
// Tap = T[a + (d+5)][2b+v] for d = u-v in {-5,-3,-1,1,3,5}, coeff
// f0T[d+v][v] = f0[v*7+d+v]; center (u=v=3) at T[a+5][2b+3] * f0[24].
// Tile T: 42x69 (vs 100x69 before). Thread = (a=lane, 4 consecutive b):
// column windows shared across b -> 64 LDS / 4 outputs. Lane stride 69: CF.
// ---------------------------------------------------------------------------
#define K4LDC 69
__global__ __launch_bounds__(256) void k4(const float* __restrict__ f0,
                                          float* __restrict__ out_hi) {
    __shared__ float T[42 * K4LDC];
    __shared__ float Osm[2][32][33];
    int bid = blockIdx.x;                        // 24576 = 2*768*16
    int jg = bid & 3, hg = (bid >> 2) & 3;
    int pbc = bid >> 4;
    int p = (pbc >= 768) ? 1 : 0;
    int bc = pbc - p * 768;
    int tid = threadIdx.x;
    int h0 = hg * 32, j0 = jg * 32;
    const float* sp = (p ? g_s1 : g_s0) + (size_t)bc * NHALF;
    int R0 = h0 + 2 * j0 - 8;
    int C0 = 6 * j0 + 2 * h0 - 19;
    for (int idx = tid; idx < 42 * K4LDC; idx += 256) {
        int rho = idx / K4LDC;
        int gam = idx - rho * K4LDC;
        int r = (R0 + rho + gam) & 127;
        int c = (C0 + 2 * rho + 3 * gam) & 255;
        T[idx] = __ldg(sp + r * 256 + c);
    }
    float f[49];
#pragma unroll
    for (int q = 0; q < 49; q++) f[q] = __ldg(f0 + q);
    __syncthreads();

    int a = tid & 31, bg = tid >> 5;             // b = bg*4 + bi
    float acc[4] = {0.f, 0.f, 0.f, 0.f};
#pragma unroll
    for (int dd = 0; dd < 6; dd++) {
        const int d = 2 * dd - 5;                // -5,-3,-1,1,3,5
        const int vmin = (d < 0) ? -d : 0;
        const int vmax = (d < 0) ? 6 : 6 - d;
        const float* Trow = &T[(a + d + 5) * K4LDC + 8 * bg];
        float vals[13];
#pragma unroll
        for (int k = vmin; k <= 6 + vmax; k++) vals[k - vmin] = Trow[k];
#pragma unroll
        for (int bi = 0; bi < 4; bi++)
#pragma unroll
            for (int v = vmin; v <= vmax; v++)
                acc[bi] += f[v * 7 + d + v] * vals[2 * bi + v - vmin];
    }
    const float* Tc = &T[(a + 5) * K4LDC + 8 * bg];
#pragma unroll
    for (int bi = 0; bi < 4; bi++) {
        float cen = f[24] * Tc[2 * bi + 3];
        Osm[0][a][bg * 4 + bi] = cen + acc[bi];  // f0^T subband
        Osm[1][a][bg * 4 + bi] = cen - acc[bi];  // f1^T subband
    }
    __syncthreads();

    size_t base = (size_t)bc * 4 * NQ;
    for (int k = tid; k < 1024; k += 256) {
        int aa = k >> 5, bb = k & 31;
        size_t pos = (size_t)(h0 + aa) * 128 + (j0 + bb);
        out_hi[base + (size_t)(2 * p + 0) * NQ + pos] = Osm[0][aa][bb];
        out_hi[base + (size_t)(2 * p + 1) * NQ + pos] = Osm[1][aa][bb];
    }
}

// ---------------------------------------------------------------------------
extern "C" void kernel_launch(void* const* d_in, const int* in_sizes, int n_in,
                              void* d_out, int out_size) {
    (void)in_sizes; (void)n_in; (void)out_size;
    const float* x  = (const float*)d_in[0];
    const float* hf = (const float*)d_in[1];
    const float* gf = (const float*)d_in[2];
    const float* f0 = (const float*)d_in[3];
    // d_in[4] (f1) is derived analytically: f1 = f0 * (-1)^(u+v) on support.
    float* out    = (float*)d_out;
    float* out_lo = out;                  // 768*128*128
    float* out_hi = out + 12582912;       // 768*4*128*128

    k1 <<<12288, 256>>>(x, hf, out_lo);
    k23<<<12288, 256>>>(x, gf, f0, out_lo);
    k4 <<<24576, 256>>>(f0, out_hi);
}